// round 7
// baseline (speedup 1.0000x reference)
#include <cuda_runtime.h>
#include <cstdint>

// Problem dims
#define B_ 32
#define S_ 64
#define T_ 64
#define E_ 128
#define H_ 256
#define V_ 32000
#define FOURH 1024
#define MPAD 2048   // padded row count for GEMM tiles (2016 real decoder rows)

// -------- device scratch (allocation-free: __device__ globals) --------
__device__ __align__(16) float  g_Xenc[MPAD * FOURH];   // enc_b + src_emb @ enc_Wih^T, rows r = s*32+b
__device__ __align__(16) float  g_Xdec[MPAD * FOURH];   // dec_b + trg_emb @ dec_Wih^T, rows r = t*32+b
__device__ __align__(16) float  g_hsT[H_][MPAD];        // decoder hidden TRANSPOSED: [u][t*32+b] (pad m>=2016 zeroed)
__device__ __align__(16) float2 g_h[2][H_ / 2][B_];     // ping-pong hidden, packed: [k2][b] = (h[2k2][b], h[2k2+1][b])
__device__ unsigned g_bar;                              // grid barrier counter (zeroed each launch)

// -------- packed f32x2 helpers (sm_103a FFMA2 = full fp32 rate) --------
static __device__ __forceinline__ unsigned long long ffma2(unsigned long long a,
                                                           unsigned long long b,
                                                           unsigned long long c) {
    unsigned long long d;
    asm("fma.rn.f32x2 %0, %1, %2, %3;" : "=l"(d) : "l"(a), "l"(b), "l"(c));
    return d;
}
static __device__ __forceinline__ unsigned long long fadd2(unsigned long long a,
                                                           unsigned long long b) {
    unsigned long long d;
    asm("add.rn.f32x2 %0, %1, %2;" : "=l"(d) : "l"(a), "l"(b));
    return d;
}
static __device__ __forceinline__ unsigned long long dup2(float a) {
    unsigned long long r;
    asm("mov.b64 %0, {%1, %1};" : "=l"(r) : "f"(a));
    return r;
}
static __device__ __forceinline__ unsigned long long pack2(float lo, float hi) {
    unsigned long long r;
    asm("mov.b64 %0, {%1, %2};" : "=l"(r) : "f"(lo), "f"(hi));
    return r;
}
static __device__ __forceinline__ float2 unpk(unsigned long long v) {
    float lo, hi;
    asm("mov.b64 {%0, %1}, %2;" : "=f"(lo), "=f"(hi) : "l"(v));
    return make_float2(lo, hi);
}

// =====================================================================
// init: zero barrier, zero h ping buffer 0, zero g_hsT pad region,
// zero out[:, 0, :]
// =====================================================================
__global__ void init_kernel(float* __restrict__ out) {
    int gt = blockIdx.x * blockDim.x + threadIdx.x;
    if (gt == 0) g_bar = 0u;
    if (gt < (H_ / 2) * B_)
        ((float2*)g_h[0])[gt] = make_float2(0.f, 0.f);
    if (gt < H_ * 32) {                          // g_hsT[u][2016..2047] = 0
        int u = gt >> 5, m = 2016 + (gt & 31);
        g_hsT[u][m] = 0.f;
    }
    const int total = B_ * (V_ / 4);
    for (int i = gt; i < total; i += gridDim.x * blockDim.x) {
        int b  = i / (V_ / 4);
        int v4 = i - b * (V_ / 4);
        ((float4*)(out + (size_t)b * T_ * V_))[v4] = make_float4(0.f, 0.f, 0.f, 0.f);
    }
}

// =====================================================================
// Xih precompute GEMM  C[2048,1024] = gathered_emb @ Wih^T (+bias)
//   MODE 0: idx=src -> g_Xenc;  MODE 1: idx=trg (t clamped) -> g_Xdec
// BM=BN=128, BK=16, 256 threads, 8x8/thread, f32x2. Stride 132 (16B ok).
// =====================================================================
template <int MODE>
__global__ __launch_bounds__(256)
void xih_kernel(const float* __restrict__ Amat, const int* __restrict__ idx,
                const float* __restrict__ Bmat, const float* __restrict__ bias) {
    const int KD = 128;
    __shared__ __align__(16) float As[16][132];
    __shared__ __align__(16) float Bs[16][132];

    const int tid = threadIdx.x;
    const int tx = tid & 15;
    const int ty = tid >> 4;
    const int n0 = blockIdx.x * 128;
    const int m0 = blockIdx.y * 128;

    const float* aP[2];
    const float* bP[2];
    int kq[2], rw[2];
#pragma unroll
    for (int l = 0; l < 2; l++) {
        int id = tid + l * 256;
        int r  = id >> 2;
        kq[l]  = (id & 3) * 4;
        rw[l]  = r;
        int rg = m0 + r;
        int tt = rg >> 5, bb = rg & 31;
        if (MODE == 1 && tt > 62) tt = 62;   // pad rows: garbage ok, never read
        aP[l] = Amat + (size_t)idx[bb * 64 + tt] * KD;
        bP[l] = Bmat + (size_t)(n0 + r) * KD;
    }

    unsigned long long acc[8][4];
#pragma unroll
    for (int i = 0; i < 8; i++)
#pragma unroll
        for (int j = 0; j < 4; j++) acc[i][j] = 0ull;

    float4 aR[2], bR[2];
#pragma unroll
    for (int l = 0; l < 2; l++) {
        aR[l] = *(const float4*)(aP[l] + kq[l]);
        bR[l] = *(const float4*)(bP[l] + kq[l]);
    }

    const int KT = KD / 16;
    for (int kt = 0; kt < KT; kt++) {
#pragma unroll
        for (int l = 0; l < 2; l++) {
            As[kq[l] + 0][rw[l]] = aR[l].x;  As[kq[l] + 1][rw[l]] = aR[l].y;
            As[kq[l] + 2][rw[l]] = aR[l].z;  As[kq[l] + 3][rw[l]] = aR[l].w;
            Bs[kq[l] + 0][rw[l]] = bR[l].x;  Bs[kq[l] + 1][rw[l]] = bR[l].y;
            Bs[kq[l] + 2][rw[l]] = bR[l].z;  Bs[kq[l] + 3][rw[l]] = bR[l].w;
        }
        __syncthreads();
        if (kt + 1 < KT) {
            int ko = (kt + 1) * 16;
#pragma unroll
            for (int l = 0; l < 2; l++) {
                aR[l] = *(const float4*)(aP[l] + ko + kq[l]);
                bR[l] = *(const float4*)(bP[l] + ko + kq[l]);
            }
        }
#pragma unroll
        for (int k = 0; k < 16; k++) {
            float4 a0 = *(const float4*)&As[k][ty * 8];
            float4 a1 = *(const float4*)&As[k][ty * 8 + 4];
            ulonglong2 b01 = *(const ulonglong2*)&Bs[k][tx * 8];
            ulonglong2 b23 = *(const ulonglong2*)&Bs[k][tx * 8 + 4];
            unsigned long long bp[4] = {b01.x, b01.y, b23.x, b23.y};
            float am[8] = {a0.x, a0.y, a0.z, a0.w, a1.x, a1.y, a1.z, a1.w};
#pragma unroll
            for (int mi = 0; mi < 8; mi++) {
                unsigned long long ad = dup2(am[mi]);
#pragma unroll
                for (int np = 0; np < 4; np++)
                    acc[mi][np] = ffma2(ad, bp[np], acc[mi][np]);
            }
        }
        __syncthreads();
    }

    float* cbase = (MODE == 0) ? g_Xenc : g_Xdec;
#pragma unroll
    for (int mi = 0; mi < 8; mi++) {
        int rg = m0 + ty * 8 + mi;
        float* cptr = cbase + (size_t)rg * FOURH;
#pragma unroll
        for (int np = 0; np < 4; np++) {
            int n = n0 + tx * 8 + np * 2;
            float2 v = unpk(acc[mi][np]);
            float2 o; o.x = v.x + bias[n]; o.y = v.y + bias[n + 1];
            *(float2*)(cptr + n) = o;
        }
    }
}

// =====================================================================
// Persistent LSTM recurrence, lane-ownership design.
// 128 CTAs x 128 threads. CTA owns units u0=2*cta .. u0+1.
// Warp w: unit ul=w&1, k-half kh=w>>1. Lane = batch b.
// Each lane accumulates ALL 4 gates for (unit, b) in two packed f32x2
// accs: (i,f) and (g,o). Weights interleaved in SMEM as float4
// {Wa[2k2],Wb[2k2],Wa[2k2+1],Wb[2k2+1]} -> LDS.128 broadcasts.
// h read straight from L2 (__ldcg LDG.64 of packed [k2][b]) — no staging.
// k-halves merged via one ulonglong2 SMEM exchange. Activation + c-update
// in-lane (c in register across both phases); 1 STG.32 h write.
// Grid barrier: fences on tid0 only.
// =====================================================================
__global__ __launch_bounds__(128)
void lstm_kernel(const float* __restrict__ WhhE, const float* __restrict__ WhhD) {
    __shared__ __align__(16) float4 sW[2][2][128];        // [ul][{if,go}][k2]  8KB
    __shared__ __align__(16) ulonglong2 sEx[2][32];       // [ul][b] (aif, ago) 1KB

    const int tid = threadIdx.x;
    const int b   = tid & 31;
    const int w   = tid >> 5;
    const int ul  = w & 1;          // unit within CTA
    const int kh  = w >> 1;         // k-half
    const int u   = blockIdx.x * 2 + ul;

    float c = 0.f;
    unsigned gen = 0;

    int stepIdx = 0;
    for (int phase = 0; phase < 2; phase++) {
        // (re)load interleaved weights for this phase
        {
            const float* W = phase ? WhhD : WhhE;
            for (int i = tid; i < 512; i += 128) {
                int ul2 = i >> 8, rem = i & 255, pr = rem >> 7, k2 = rem & 127;
                int uu = blockIdx.x * 2 + ul2;
                int g0 = pr * 2, g1 = pr * 2 + 1;
                float2 wa = *(const float2*)&W[(size_t)(g0 * 256 + uu) * 256 + 2 * k2];
                float2 wb = *(const float2*)&W[(size_t)(g1 * 256 + uu) * 256 + 2 * k2];
                sW[ul2][pr][k2] = make_float4(wa.x, wb.x, wa.y, wb.y);
            }
        }
        __syncthreads();

        const int nsteps = phase ? 63 : 64;
        const float* X = phase ? g_Xdec : g_Xenc;
        for (int s = 0; s < nsteps; s++) {
            const int p = stepIdx & 1;

            // init accs; kh=0 warps fold in the x contribution
            unsigned long long aif, ago;
            if (kh == 0) {
                size_t xr = (size_t)((s << 5) + b) * FOURH + u;
                float xi = X[xr];
                float xf = X[xr + 256];
                float xg = X[xr + 512];
                float xo = X[xr + 768];
                aif = pack2(xi, xf);
                ago = pack2(xg, xo);
            } else {
                aif = 0ull; ago = 0ull;
            }
            unsigned long long aifB = 0ull, agoB = 0ull;

            const unsigned long long* hrow =
                (const unsigned long long*)&g_h[p][0][0];
            const int k0 = kh * 64;
#pragma unroll 8
            for (int k2 = k0; k2 < k0 + 64; k2++) {
                unsigned long long h2 = __ldcg(&hrow[k2 * 32 + b]);
                float2 hh = unpk(h2);
                unsigned long long h0d = dup2(hh.x);
                unsigned long long h1d = dup2(hh.y);
                ulonglong2 wif = *(const ulonglong2*)&sW[ul][0][k2];
                ulonglong2 wgo = *(const ulonglong2*)&sW[ul][1][k2];
                aif  = ffma2(wif.x, h0d, aif);
                aifB = ffma2(wif.y, h1d, aifB);
                ago  = ffma2(wgo.x, h0d, ago);
                agoB = ffma2(wgo.y, h1d, agoB);
            }
            aif = fadd2(aif, aifB);
            ago = fadd2(ago, agoB);

            // merge k-halves
            if (kh == 1) sEx[ul][b] = make_ulonglong2(aif, ago);
            __syncthreads();
            if (kh == 0) {
                ulonglong2 e = sEx[ul][b];
                aif = fadd2(aif, e.x);
                ago = fadd2(ago, e.y);
                float2 vif = unpk(aif), vgo = unpk(ago);
                float si = 1.f / (1.f + __expf(-vif.x));
                float sf = 1.f / (1.f + __expf(-vif.y));
                float so = 1.f / (1.f + __expf(-vgo.y));
                c = sf * c + si * tanhf(vgo.x);
                float hv = so * tanhf(c);
                ((float*)&g_h[p ^ 1][blockIdx.x][b])[ul] = hv;   // packed [k2][b]
                if (phase) g_hsT[u][(s << 5) + b] = hv;          // coalesced
            }
            __syncthreads();

            // grid barrier (counter zeroed each launch by init_kernel)
            gen++;
            if (tid == 0) {
                __threadfence();                  // release
                atomicAdd(&g_bar, 1u);
                const unsigned target = gen * 128u;
                while (*((volatile unsigned*)&g_bar) < target) { }
                __threadfence();                  // acquire
            }
            __syncthreads();
            stepIdx++;
        }
    }
}

// =====================================================================
// FC GEMM: g_hsT^T[2048,256] @ fc_W[32000,256]^T + fc_b -> scatter
// BM=128, BN=256, BK=16, 256 threads, 16x8 per-thread tile, f32x2.
// A from transposed g_hsT: coalesced LDG.128 + aligned STS.128
// (As stride 132 floats = 528B, 16B-aligned). B path unchanged (8B LDS).
// =====================================================================
__global__ __launch_bounds__(256)
void fc_kernel(const float* __restrict__ Bmat, const float* __restrict__ bias,
               float* __restrict__ out) {
    __shared__ __align__(16) float As[16][132];
    __shared__ __align__(16) float Bs[16][258];

    const int tid = threadIdx.x;
    const int tx = tid & 31;        // N: cols tx*4..+3 and 128+tx*4..+3
    const int ty = tid >> 5;        // M: rows ty*16..+15
    const int n0 = blockIdx.x * 256;
    const int m0 = blockIdx.y * 128;

    // A loaders: 2 slots/thread from g_hsT[k][m] (row-contiguous in m)
    const float* aP[2]; int ak[2], aj[2];
#pragma unroll
    for (int l = 0; l < 2; l++) {
        int id = tid + l * 256;
        ak[l] = id >> 5;                  // k row 0..15
        aj[l] = id & 31;                  // m-chunk 0..31
        aP[l] = &g_hsT[ak[l]][m0 + aj[l] * 4];
    }
    // B loaders: 4 slots/thread
    const float* bP[4]; int bkq[4], brw[4];
#pragma unroll
    for (int l = 0; l < 4; l++) {
        int id = tid + l * 256;
        brw[l] = id >> 2;                 // 0..255
        bkq[l] = (id & 3) * 4;
        bP[l]  = Bmat + (size_t)(n0 + brw[l]) * H_ + bkq[l];
    }

    unsigned long long acc[16][4];
#pragma unroll
    for (int i = 0; i < 16; i++)
#pragma unroll
        for (int j = 0; j < 4; j++) acc[i][j] = 0ull;

    float4 aR[2], bR[4];
#pragma unroll
    for (int l = 0; l < 2; l++) aR[l] = *(const float4*)(aP[l]);
#pragma unroll
    for (int l = 0; l < 4; l++) bR[l] = *(const float4*)(bP[l]);

    const int KT = H_ / 16;   // 16 k-tiles
    for (int kt = 0; kt < KT; kt++) {
#pragma unroll
        for (int l = 0; l < 2; l++)
            *(float4*)&As[ak[l]][aj[l] * 4] = aR[l];     // aligned STS.128
#pragma unroll
        for (int l = 0; l < 4; l++) {
            Bs[bkq[l] + 0][brw[l]] = bR[l].x;  Bs[bkq[l] + 1][brw[l]] = bR[l].y;
            Bs[bkq[l] + 2][brw[l]] = bR[l].z;  Bs[bkq[l] + 3][brw[l]] = bR[l].w;
        }
        __syncthreads();
        if (kt + 1 < KT) {
#pragma unroll
            for (int l = 0; l < 2; l++)
                aR[l] = *(const float4*)(aP[l] + (size_t)(kt + 1) * 16 * MPAD);
            int ko = (kt + 1) * 16;
#pragma unroll
            for (int l = 0; l < 4; l++) bR[l] = *(const float4*)(bP[l] + ko);
        }
#pragma unroll
        for (int k = 0; k < 16; k++) {
            // B fragment: 8 cols as 4 packed pairs — 8B loads (8B-aligned all k)
            unsigned long long bp[4];
            bp[0] = *(const unsigned long long*)&Bs[k][tx * 4];
            bp[1] = *(const unsigned long long*)&Bs[k][tx * 4 + 2];
            bp[2] = *(const unsigned long long*)&Bs[k][128 + tx * 4];
            bp[3] = *(const unsigned long long*)&Bs[k][128 + tx * 4 + 2];
            // A fragment: 16 rows via 4 broadcast LDS.128 (16B-aligned)
            float4 a0 = *(const float4*)&As[k][ty * 16 + 0];
            float4 a1 = *(const float4*)&As[k][ty * 16 + 4];
            float4 a2 = *(const float4*)&As[k][ty * 16 + 8];
            float4 a3 = *(const float4*)&As[k][ty * 16 + 12];
            float am[16] = {a0.x, a0.y, a0.z, a0.w, a1.x, a1.y, a1.z, a1.w,
                            a2.x, a2.y, a2.z, a2.w, a3.x, a3.y, a3.z, a3.w};
#pragma unroll
            for (int mi = 0; mi < 16; mi++) {
                unsigned long long ad = dup2(am[mi]);
#pragma unroll
                for (int np = 0; np < 4; np++)
                    acc[mi][np] = ffma2(ad, bp[np], acc[mi][np]);
            }
        }
        __syncthreads();
    }

    // epilogue: bias + scatter out[b][t+1][v], skip pad rows (t=63)
    float4 bias0 = *(const float4*)(bias + n0 + tx * 4);
    float4 bias1 = *(const float4*)(bias + n0 + 128 + tx * 4);
#pragma unroll
    for (int mi = 0; mi < 16; mi++) {
        int rg = m0 + ty * 16 + mi;
        if (rg >= 2016) continue;
        int bb = rg & 31, t = rg >> 5;
        float* cptr = out + (size_t)bb * ((size_t)T_ * V_) + (size_t)(t + 1) * V_;
        float2 v0 = unpk(acc[mi][0]), v1 = unpk(acc[mi][1]);
        float2 v2 = unpk(acc[mi][2]), v3 = unpk(acc[mi][3]);
        float4 o0 = make_float4(v0.x + bias0.x, v0.y + bias0.y,
                                v1.x + bias0.z, v1.y + bias0.w);
        float4 o1 = make_float4(v2.x + bias1.x, v2.y + bias1.y,
                                v3.x + bias1.z, v3.y + bias1.w);
        *(float4*)(cptr + n0 + tx * 4)       = o0;
        *(float4*)(cptr + n0 + 128 + tx * 4) = o1;
    }
}

// =====================================================================
extern "C" void kernel_launch(void* const* d_in, const int* in_sizes, int n_in,
                              void* d_out, int out_size) {
    const int*   src  = (const int*)d_in[0];
    const int*   trg  = (const int*)d_in[1];
    const float* eemb = (const float*)d_in[2];
    const float* eWih = (const float*)d_in[3];
    const float* eWhh = (const float*)d_in[4];
    const float* eb   = (const float*)d_in[5];
    const float* demb = (const float*)d_in[6];
    const float* dWih = (const float*)d_in[7];
    const float* dWhh = (const float*)d_in[8];
    const float* db   = (const float*)d_in[9];
    const float* fcW  = (const float*)d_in[10];
    const float* fcb  = (const float*)d_in[11];
    float* out = (float*)d_out;

    init_kernel<<<256, 256>>>(out);
    xih_kernel<0><<<dim3(8, 16), 256>>>(eemb, src, eWih, eb);
    xih_kernel<1><<<dim3(8, 16), 256>>>(demb, trg, dWih, db);
    lstm_kernel<<<128, 128>>>(eWhh, dWhh);
    fc_kernel<<<dim3(125, 16), 256>>>(fcW, fcb, out);
}

// round 8
// speedup vs baseline: 1.3315x; 1.3315x over previous
#include <cuda_runtime.h>
#include <cstdint>

// Problem dims
#define B_ 32
#define S_ 64
#define T_ 64
#define E_ 128
#define H_ 256
#define V_ 32000
#define FOURH 1024
#define MPAD 2048   // padded row count for GEMM tiles (2016 real decoder rows)

// LSTM cluster config: 16 clusters x 8 CTAs; cluster owns 2 batches,
// CTA rank owns 32 hidden units (128 gate rows, 128KB Whh slice in SMEM).
#define CSIZE 8
#define LSTM_CTAS 128
// dynamic SMEM layout for lstm kernel
#define SW_BYTES   131072                 // float4 sW[64][128]
#define HS_BYTES   4096                   // float4 hS[2][128]
#define GB_BYTES   1024                   // float gbuf[4][32][2]
#define LSTM_SMEM  (SW_BYTES + HS_BYTES + GB_BYTES)

// -------- device scratch (allocation-free: __device__ globals) --------
__device__ __align__(16) float g_Xenc[MPAD * FOURH];   // enc_b + src_emb @ enc_Wih^T, rows r = s*32+b
__device__ __align__(16) float g_Xdec[MPAD * FOURH];   // dec_b + trg_emb @ dec_Wih^T, rows r = t*32+b
__device__ __align__(16) float g_hsT[H_][MPAD];        // decoder hidden TRANSPOSED: [u][t*32+b] (pad m>=2016 zeroed)

// -------- packed f32x2 helpers (sm_103a FFMA2 = full fp32 rate) --------
static __device__ __forceinline__ unsigned long long ffma2(unsigned long long a,
                                                           unsigned long long b,
                                                           unsigned long long c) {
    unsigned long long d;
    asm("fma.rn.f32x2 %0, %1, %2, %3;" : "=l"(d) : "l"(a), "l"(b), "l"(c));
    return d;
}
static __device__ __forceinline__ unsigned long long fadd2(unsigned long long a,
                                                           unsigned long long b) {
    unsigned long long d;
    asm("add.rn.f32x2 %0, %1, %2;" : "=l"(d) : "l"(a), "l"(b));
    return d;
}
static __device__ __forceinline__ unsigned long long dup2(float a) {
    unsigned long long r;
    asm("mov.b64 %0, {%1, %1};" : "=l"(r) : "f"(a));
    return r;
}
static __device__ __forceinline__ float2 unpk(unsigned long long v) {
    float lo, hi;
    asm("mov.b64 {%0, %1}, %2;" : "=f"(lo), "=f"(hi) : "l"(v));
    return make_float2(lo, hi);
}

// -------- cluster helpers --------
static __device__ __forceinline__ uint32_t ctarank() {
    uint32_t r; asm("mov.u32 %0, %%cluster_ctarank;" : "=r"(r)); return r;
}
static __device__ __forceinline__ uint32_t smem_u32(const void* p) {
    uint32_t a;
    asm("{ .reg .u64 t; cvta.to.shared.u64 t, %1; cvt.u32.u64 %0, t; }"
        : "=r"(a) : "l"(p));
    return a;
}
static __device__ __forceinline__ void st_cluster_f32(uint32_t laddr, uint32_t rank, float v) {
    uint32_t raddr;
    asm volatile("mapa.shared::cluster.u32 %0, %1, %2;" : "=r"(raddr) : "r"(laddr), "r"(rank));
    asm volatile("st.shared::cluster.f32 [%0], %1;" :: "r"(raddr), "f"(v) : "memory");
}
static __device__ __forceinline__ void cluster_sync() {
    asm volatile("barrier.cluster.arrive.aligned;" ::: "memory");
    asm volatile("barrier.cluster.wait.aligned;" ::: "memory");
}

// =====================================================================
// init: zero g_hsT pad rows, zero out[:, 0, :]
// =====================================================================
__global__ void init_kernel(float* __restrict__ out) {
    int gt = blockIdx.x * blockDim.x + threadIdx.x;
    if (gt < H_ * 32) {                          // g_hsT[u][2016..2047] = 0
        int u = gt >> 5, m = 2016 + (gt & 31);
        g_hsT[u][m] = 0.f;
    }
    const int total = B_ * (V_ / 4);
    for (int i = gt; i < total; i += gridDim.x * blockDim.x) {
        int b  = i / (V_ / 4);
        int v4 = i - b * (V_ / 4);
        ((float4*)(out + (size_t)b * T_ * V_))[v4] = make_float4(0.f, 0.f, 0.f, 0.f);
    }
}

// =====================================================================
// Xih precompute GEMM  C[2048,1024] = gathered_emb @ Wih^T (+bias)
//   MODE 0: idx=src -> g_Xenc;  MODE 1: idx=trg (t clamped) -> g_Xdec
// BM=BN=128, BK=16, 256 threads, 8x8/thread, f32x2. Stride 132 (16B ok).
// =====================================================================
template <int MODE>
__global__ __launch_bounds__(256)
void xih_kernel(const float* __restrict__ Amat, const int* __restrict__ idx,
                const float* __restrict__ Bmat, const float* __restrict__ bias) {
    const int KD = 128;
    __shared__ __align__(16) float As[16][132];
    __shared__ __align__(16) float Bs[16][132];

    const int tid = threadIdx.x;
    const int tx = tid & 15;
    const int ty = tid >> 4;
    const int n0 = blockIdx.x * 128;
    const int m0 = blockIdx.y * 128;

    const float* aP[2];
    const float* bP[2];
    int kq[2], rw[2];
#pragma unroll
    for (int l = 0; l < 2; l++) {
        int id = tid + l * 256;
        int r  = id >> 2;
        kq[l]  = (id & 3) * 4;
        rw[l]  = r;
        int rg = m0 + r;
        int tt = rg >> 5, bb = rg & 31;
        if (MODE == 1 && tt > 62) tt = 62;   // pad rows: garbage ok, never read
        aP[l] = Amat + (size_t)idx[bb * 64 + tt] * KD;
        bP[l] = Bmat + (size_t)(n0 + r) * KD;
    }

    unsigned long long acc[8][4];
#pragma unroll
    for (int i = 0; i < 8; i++)
#pragma unroll
        for (int j = 0; j < 4; j++) acc[i][j] = 0ull;

    float4 aR[2], bR[2];
#pragma unroll
    for (int l = 0; l < 2; l++) {
        aR[l] = *(const float4*)(aP[l] + kq[l]);
        bR[l] = *(const float4*)(bP[l] + kq[l]);
    }

    const int KT = KD / 16;
    for (int kt = 0; kt < KT; kt++) {
#pragma unroll
        for (int l = 0; l < 2; l++) {
            As[kq[l] + 0][rw[l]] = aR[l].x;  As[kq[l] + 1][rw[l]] = aR[l].y;
            As[kq[l] + 2][rw[l]] = aR[l].z;  As[kq[l] + 3][rw[l]] = aR[l].w;
            Bs[kq[l] + 0][rw[l]] = bR[l].x;  Bs[kq[l] + 1][rw[l]] = bR[l].y;
            Bs[kq[l] + 2][rw[l]] = bR[l].z;  Bs[kq[l] + 3][rw[l]] = bR[l].w;
        }
        __syncthreads();
        if (kt + 1 < KT) {
            int ko = (kt + 1) * 16;
#pragma unroll
            for (int l = 0; l < 2; l++) {
                aR[l] = *(const float4*)(aP[l] + ko + kq[l]);
                bR[l] = *(const float4*)(bP[l] + ko + kq[l]);
            }
        }
#pragma unroll
        for (int k = 0; k < 16; k++) {
            float4 a0 = *(const float4*)&As[k][ty * 8];
            float4 a1 = *(const float4*)&As[k][ty * 8 + 4];
            ulonglong2 b01 = *(const ulonglong2*)&Bs[k][tx * 8];
            ulonglong2 b23 = *(const ulonglong2*)&Bs[k][tx * 8 + 4];
            unsigned long long bp[4] = {b01.x, b01.y, b23.x, b23.y};
            float am[8] = {a0.x, a0.y, a0.z, a0.w, a1.x, a1.y, a1.z, a1.w};
#pragma unroll
            for (int mi = 0; mi < 8; mi++) {
                unsigned long long ad = dup2(am[mi]);
#pragma unroll
                for (int np = 0; np < 4; np++)
                    acc[mi][np] = ffma2(ad, bp[np], acc[mi][np]);
            }
        }
        __syncthreads();
    }

    float* cbase = (MODE == 0) ? g_Xenc : g_Xdec;
#pragma unroll
    for (int mi = 0; mi < 8; mi++) {
        int rg = m0 + ty * 8 + mi;
        float* cptr = cbase + (size_t)rg * FOURH;
#pragma unroll
        for (int np = 0; np < 4; np++) {
            int n = n0 + tx * 8 + np * 2;
            float2 v = unpk(acc[mi][np]);
            float2 o; o.x = v.x + bias[n]; o.y = v.y + bias[n + 1];
            *(float2*)(cptr + n) = o;
        }
    }
}

// =====================================================================
// Persistent cluster LSTM. 16 clusters x 8 CTAs x 128 threads.
// Cluster c: batches {2c, 2c+1}. CTA rank r: Whh rows for units
// [32r, 32r+32) -> 128 gate rows x 256 k = 128KB resident in SMEM.
// Thread tid = gate row (g=tid>>5, ul=tid&31); computes the gate preact
// for BOTH batches as one packed f32x2 accumulator.
// h replicated per-CTA in SMEM, double-buffered float4 hS[2][128]:
//   hS[p][k2] = (h[2k2][b0], h[2k2][b1], h[2k2+1][b0], h[2k2+1][b1]).
// After gates: threads 0..63 own (unit, batch); c in register; new h
// pushed to all 8 peers via mapa + st.shared::cluster; ONE
// barrier.cluster per step (double buffering makes it sufficient).
// =====================================================================
__global__ __launch_bounds__(128) __cluster_dims__(CSIZE, 1, 1)
void lstm_kernel(const float* __restrict__ WhhE, const float* __restrict__ WhhD) {
    extern __shared__ __align__(16) char smem[];
    float4* sW   = (float4*)smem;                        // [64][128] : sW[kg][tid] = W[row(tid)][4kg..4kg+3]
    float4* hS   = (float4*)(smem + SW_BYTES);           // [2][128]
    float*  gbuf = (float*)(smem + SW_BYTES + HS_BYTES); // [4][32][2]

    const int tid  = threadIdx.x;
    const uint32_t rank = ctarank();
    const int cid  = blockIdx.x >> 3;      // cluster id 0..15
    const int g    = tid >> 5;             // gate 0..3
    const int ul   = tid & 31;             // unit within CTA block
    const int j    = g * 256 + (int)rank * 32 + ul;   // global gate row
    const int b0   = cid * 2;              // global batch base

    const uint32_t hS_u32 = smem_u32(hS);

    // zero h buffer p=0 (own copy)
    hS[tid] = make_float4(0.f, 0.f, 0.f, 0.f);

    float c = 0.f;                         // cell state for owners (tid<64)
    int stepIdx = 0;

    for (int phase = 0; phase < 2; phase++) {
        // load this phase's Whh slice: thread's own row, 64 x LDG.128
        {
            const float4* wrow = (const float4*)((phase ? WhhD : WhhE) + (size_t)j * H_);
#pragma unroll 8
            for (int kg = 0; kg < 64; kg++)
                sW[kg * 128 + tid] = __ldg(&wrow[kg]);
        }
        __syncthreads();   // also covers hS[0] zero on phase 0

        const int nsteps = phase ? 63 : 64;
        const float* X = phase ? g_Xdec : g_Xenc;

        for (int s = 0; s < nsteps; s++) {
            const int p = stepIdx & 1;

            // x contributions (independent of h; issue early)
            float x0 = X[(size_t)((s << 5) + b0    ) * FOURH + j];
            float x1 = X[(size_t)((s << 5) + b0 + 1) * FOURH + j];

            unsigned long long acc0 = 0ull, acc1 = 0ull;
            const ulonglong2* hp = (const ulonglong2*)(hS + p * 128);
#pragma unroll 8
            for (int kg = 0; kg < 64; kg++) {
                float4 w4 = sW[kg * 128 + tid];       // lane-distinct LDS.128
                ulonglong2 ha = hp[2 * kg];           // broadcast: k=4kg,4kg+1
                ulonglong2 hb = hp[2 * kg + 1];       // broadcast: k=4kg+2,4kg+3
                acc0 = ffma2(dup2(w4.x), ha.x, acc0);
                acc1 = ffma2(dup2(w4.y), ha.y, acc1);
                acc0 = ffma2(dup2(w4.z), hb.x, acc0);
                acc1 = ffma2(dup2(w4.w), hb.y, acc1);
            }
            float2 gv = unpk(fadd2(acc0, acc1));      // (preact_b0, preact_b1)
            *(float2*)&gbuf[tid * 2] = make_float2(gv.x + x0, gv.y + x1);
            __syncthreads();

            if (tid < 64) {                 // owner of (unit ul, batch bb)
                int uu = tid & 31;
                int bb = tid >> 5;          // 0 or 1
                float ig = gbuf[(0 * 32 + uu) * 2 + bb];
                float fg = gbuf[(1 * 32 + uu) * 2 + bb];
                float gg = gbuf[(2 * 32 + uu) * 2 + bb];
                float og = gbuf[(3 * 32 + uu) * 2 + bb];
                float si = 1.f / (1.f + __expf(-ig));
                float sf = 1.f / (1.f + __expf(-fg));
                float so = 1.f / (1.f + __expf(-og));
                c = sf * c + si * tanhf(gg);
                float hv = so * tanhf(c);

                // push to all 8 cluster CTAs' hS[p^1]
                int ug = (int)rank * 32 + uu;
                uint32_t off = hS_u32 + (uint32_t)(((p ^ 1) * 128 + (ug >> 1)) * 16
                                                   + ((ug & 1) * 2 + bb) * 4);
#pragma unroll
                for (int r = 0; r < CSIZE; r++)
                    st_cluster_f32(off, (uint32_t)r, hv);

                if (phase) g_hsT[ug][(s << 5) + b0 + bb] = hv;
            }

            // one cluster barrier per step (release/acquire covers DSMEM stores)
            cluster_sync();
            stepIdx++;
        }
    }
}

// =====================================================================
// FC GEMM: g_hsT^T[2048,256] @ fc_W[32000,256]^T + fc_b -> scatter
// BM=128, BN=256, BK=16, 256 threads, 16x8 per-thread tile, f32x2.
// A from transposed g_hsT: coalesced LDG.128 + aligned STS.128
// (As stride 132 floats = 528B, 16B-aligned). B: 8B LDS (stride 258).
// =====================================================================
__global__ __launch_bounds__(256)
void fc_kernel(const float* __restrict__ Bmat, const float* __restrict__ bias,
               float* __restrict__ out) {
    __shared__ __align__(16) float As[16][132];
    __shared__ __align__(16) float Bs[16][258];

    const int tid = threadIdx.x;
    const int tx = tid & 31;        // N: cols tx*4..+3 and 128+tx*4..+3
    const int ty = tid >> 5;        // M: rows ty*16..+15
    const int n0 = blockIdx.x * 256;
    const int m0 = blockIdx.y * 128;

    // A loaders: 2 slots/thread from g_hsT[k][m] (row-contiguous in m)
    const float* aP[2]; int ak[2], aj[2];
#pragma unroll
    for (int l = 0; l < 2; l++) {
        int id = tid + l * 256;
        ak[l] = id >> 5;                  // k row 0..15
        aj[l] = id & 31;                  // m-chunk 0..31
        aP[l] = &g_hsT[ak[l]][m0 + aj[l] * 4];
    }
    // B loaders: 4 slots/thread
    const float* bP[4]; int bkq[4], brw[4];
#pragma unroll
    for (int l = 0; l < 4; l++) {
        int id = tid + l * 256;
        brw[l] = id >> 2;                 // 0..255
        bkq[l] = (id & 3) * 4;
        bP[l]  = Bmat + (size_t)(n0 + brw[l]) * H_ + bkq[l];
    }

    unsigned long long acc[16][4];
#pragma unroll
    for (int i = 0; i < 16; i++)
#pragma unroll
        for (int j = 0; j < 4; j++) acc[i][j] = 0ull;

    float4 aR[2], bR[4];
#pragma unroll
    for (int l = 0; l < 2; l++) aR[l] = *(const float4*)(aP[l]);
#pragma unroll
    for (int l = 0; l < 4; l++) bR[l] = *(const float4*)(bP[l]);

    const int KT = H_ / 16;   // 16 k-tiles
    for (int kt = 0; kt < KT; kt++) {
#pragma unroll
        for (int l = 0; l < 2; l++)
            *(float4*)&As[ak[l]][aj[l] * 4] = aR[l];     // aligned STS.128
#pragma unroll
        for (int l = 0; l < 4; l++) {
            Bs[bkq[l] + 0][brw[l]] = bR[l].x;  Bs[bkq[l] + 1][brw[l]] = bR[l].y;
            Bs[bkq[l] + 2][brw[l]] = bR[l].z;  Bs[bkq[l] + 3][brw[l]] = bR[l].w;
        }
        __syncthreads();
        if (kt + 1 < KT) {
#pragma unroll
            for (int l = 0; l < 2; l++)
                aR[l] = *(const float4*)(aP[l] + (size_t)(kt + 1) * 16 * MPAD);
            int ko = (kt + 1) * 16;
#pragma unroll
            for (int l = 0; l < 4; l++) bR[l] = *(const float4*)(bP[l] + ko);
        }
#pragma unroll
        for (int k = 0; k < 16; k++) {
            // B fragment: 8 cols as 4 packed pairs — 8B loads (8B-aligned all k)
            unsigned long long bp[4];
            bp[0] = *(const unsigned long long*)&Bs[k][tx * 4];
            bp[1] = *(const unsigned long long*)&Bs[k][tx * 4 + 2];
            bp[2] = *(const unsigned long long*)&Bs[k][128 + tx * 4];
            bp[3] = *(const unsigned long long*)&Bs[k][128 + tx * 4 + 2];
            // A fragment: 16 rows via 4 broadcast LDS.128 (16B-aligned)
            float4 a0 = *(const float4*)&As[k][ty * 16 + 0];
            float4 a1 = *(const float4*)&As[k][ty * 16 + 4];
            float4 a2 = *(const float4*)&As[k][ty * 16 + 8];
            float4 a3 = *(const float4*)&As[k][ty * 16 + 12];
            float am[16] = {a0.x, a0.y, a0.z, a0.w, a1.x, a1.y, a1.z, a1.w,
                            a2.x, a2.y, a2.z, a2.w, a3.x, a3.y, a3.z, a3.w};
#pragma unroll
            for (int mi = 0; mi < 16; mi++) {
                unsigned long long ad = dup2(am[mi]);
#pragma unroll
                for (int np = 0; np < 4; np++)
                    acc[mi][np] = ffma2(ad, bp[np], acc[mi][np]);
            }
        }
        __syncthreads();
    }

    // epilogue: bias + scatter out[b][t+1][v], skip pad rows (t=63)
    float4 bias0 = *(const float4*)(bias + n0 + tx * 4);
    float4 bias1 = *(const float4*)(bias + n0 + 128 + tx * 4);
#pragma unroll
    for (int mi = 0; mi < 16; mi++) {
        int rg = m0 + ty * 16 + mi;
        if (rg >= 2016) continue;
        int bb = rg & 31, t = rg >> 5;
        float* cptr = out + (size_t)bb * ((size_t)T_ * V_) + (size_t)(t + 1) * V_;
        float2 v0 = unpk(acc[mi][0]), v1 = unpk(acc[mi][1]);
        float2 v2 = unpk(acc[mi][2]), v3 = unpk(acc[mi][3]);
        float4 o0 = make_float4(v0.x + bias0.x, v0.y + bias0.y,
                                v1.x + bias0.z, v1.y + bias0.w);
        float4 o1 = make_float4(v2.x + bias1.x, v2.y + bias1.y,
                                v3.x + bias1.z, v3.y + bias1.w);
        *(float4*)(cptr + n0 + tx * 4)       = o0;
        *(float4*)(cptr + n0 + 128 + tx * 4) = o1;
    }
}

// =====================================================================
extern "C" void kernel_launch(void* const* d_in, const int* in_sizes, int n_in,
                              void* d_out, int out_size) {
    const int*   src  = (const int*)d_in[0];
    const int*   trg  = (const int*)d_in[1];
    const float* eemb = (const float*)d_in[2];
    const float* eWih = (const float*)d_in[3];
    const float* eWhh = (const float*)d_in[4];
    const float* eb   = (const float*)d_in[5];
    const float* demb = (const float*)d_in[6];
    const float* dWih = (const float*)d_in[7];
    const float* dWhh = (const float*)d_in[8];
    const float* db   = (const float*)d_in[9];
    const float* fcW  = (const float*)d_in[10];
    const float* fcb  = (const float*)d_in[11];
    float* out = (float*)d_out;

    cudaFuncSetAttribute(lstm_kernel,
                         cudaFuncAttributeMaxDynamicSharedMemorySize, LSTM_SMEM);

    init_kernel<<<256, 256>>>(out);
    xih_kernel<0><<<dim3(8, 16), 256>>>(eemb, src, eWih, eb);
    xih_kernel<1><<<dim3(8, 16), 256>>>(demb, trg, dWih, db);
    lstm_kernel<<<LSTM_CTAS, 128, LSTM_SMEM>>>(eWhh, dWhh);
    fc_kernel<<<dim3(125, 16), 256>>>(fcW, fcb, out);
}

// round 9
// speedup vs baseline: 1.5566x; 1.1690x over previous
#include <cuda_runtime.h>
#include <cstdint>

// Problem dims
#define B_ 32
#define S_ 64
#define T_ 64
#define E_ 128
#define H_ 256
#define V_ 32000
#define FOURH 1024
#define MPAD 2048   // padded row count for GEMM tiles (2016 real decoder rows)

// LSTM cluster config: 16 clusters x 8 CTAs; cluster owns 2 batches,
// CTA rank owns 32 hidden units (128 gate rows). Whh slice lives in
// REGISTERS: 256 threads x 64 f32x2 regs = 128KB per CTA.
#define CSIZE 8
#define LSTM_CTAS 128

// -------- device scratch (allocation-free: __device__ globals) --------
__device__ __align__(16) float g_Xenc[MPAD * FOURH];   // enc_b + src_emb @ enc_Wih^T, rows r = s*32+b
__device__ __align__(16) float g_Xdec[MPAD * FOURH];   // dec_b + trg_emb @ dec_Wih^T, rows r = t*32+b
__device__ __align__(16) float g_hsT[H_][MPAD];        // decoder hidden TRANSPOSED: [u][t*32+b] (pad m>=2016 zeroed)

// -------- packed f32x2 helpers (sm_103a FFMA2 = full fp32 rate) --------
static __device__ __forceinline__ unsigned long long ffma2(unsigned long long a,
                                                           unsigned long long b,
                                                           unsigned long long c) {
    unsigned long long d;
    asm("fma.rn.f32x2 %0, %1, %2, %3;" : "=l"(d) : "l"(a), "l"(b), "l"(c));
    return d;
}
static __device__ __forceinline__ unsigned long long dup2(float a) {
    unsigned long long r;
    asm("mov.b64 %0, {%1, %1};" : "=l"(r) : "f"(a));
    return r;
}
static __device__ __forceinline__ float2 unpk(unsigned long long v) {
    float lo, hi;
    asm("mov.b64 {%0, %1}, %2;" : "=f"(lo), "=f"(hi) : "l"(v));
    return make_float2(lo, hi);
}

// -------- cluster helpers --------
static __device__ __forceinline__ uint32_t ctarank() {
    uint32_t r; asm("mov.u32 %0, %%cluster_ctarank;" : "=r"(r)); return r;
}
static __device__ __forceinline__ uint32_t smem_u32(const void* p) {
    uint32_t a;
    asm("{ .reg .u64 t; cvta.to.shared.u64 t, %1; cvt.u32.u64 %0, t; }"
        : "=r"(a) : "l"(p));
    return a;
}
static __device__ __forceinline__ void st_cluster_f32(uint32_t laddr, uint32_t rank, float v) {
    uint32_t raddr;
    asm volatile("mapa.shared::cluster.u32 %0, %1, %2;" : "=r"(raddr) : "r"(laddr), "r"(rank));
    asm volatile("st.shared::cluster.f32 [%0], %1;" :: "r"(raddr), "f"(v) : "memory");
}
static __device__ __forceinline__ void cluster_sync() {
    asm volatile("barrier.cluster.arrive.aligned;" ::: "memory");
    asm volatile("barrier.cluster.wait.aligned;" ::: "memory");
}

// =====================================================================
// init: zero g_hsT pad rows, zero out[:, 0, :]
// =====================================================================
__global__ void init_kernel(float* __restrict__ out) {
    int gt = blockIdx.x * blockDim.x + threadIdx.x;
    if (gt < H_ * 32) {                          // g_hsT[u][2016..2047] = 0
        int u = gt >> 5, m = 2016 + (gt & 31);
        g_hsT[u][m] = 0.f;
    }
    const int total = B_ * (V_ / 4);
    for (int i = gt; i < total; i += gridDim.x * blockDim.x) {
        int b  = i / (V_ / 4);
        int v4 = i - b * (V_ / 4);
        ((float4*)(out + (size_t)b * T_ * V_))[v4] = make_float4(0.f, 0.f, 0.f, 0.f);
    }
}

// =====================================================================
// Xih precompute GEMM  C[2048,1024] = gathered_emb @ Wih^T (+bias)
//   MODE 0: idx=src -> g_Xenc;  MODE 1: idx=trg (t clamped) -> g_Xdec
// BM=BN=128, BK=16, 256 threads, 8x8/thread, f32x2. Stride 132 (16B ok).
// =====================================================================
template <int MODE>
__global__ __launch_bounds__(256)
void xih_kernel(const float* __restrict__ Amat, const int* __restrict__ idx,
                const float* __restrict__ Bmat, const float* __restrict__ bias) {
    const int KD = 128;
    __shared__ __align__(16) float As[16][132];
    __shared__ __align__(16) float Bs[16][132];

    const int tid = threadIdx.x;
    const int tx = tid & 15;
    const int ty = tid >> 4;
    const int n0 = blockIdx.x * 128;
    const int m0 = blockIdx.y * 128;

    const float* aP[2];
    const float* bP[2];
    int kq[2], rw[2];
#pragma unroll
    for (int l = 0; l < 2; l++) {
        int id = tid + l * 256;
        int r  = id >> 2;
        kq[l]  = (id & 3) * 4;
        rw[l]  = r;
        int rg = m0 + r;
        int tt = rg >> 5, bb = rg & 31;
        if (MODE == 1 && tt > 62) tt = 62;   // pad rows: garbage ok, never read
        aP[l] = Amat + (size_t)idx[bb * 64 + tt] * KD;
        bP[l] = Bmat + (size_t)(n0 + r) * KD;
    }

    unsigned long long acc[8][4];
#pragma unroll
    for (int i = 0; i < 8; i++)
#pragma unroll
        for (int j = 0; j < 4; j++) acc[i][j] = 0ull;

    float4 aR[2], bR[2];
#pragma unroll
    for (int l = 0; l < 2; l++) {
        aR[l] = *(const float4*)(aP[l] + kq[l]);
        bR[l] = *(const float4*)(bP[l] + kq[l]);
    }

    const int KT = KD / 16;
    for (int kt = 0; kt < KT; kt++) {
#pragma unroll
        for (int l = 0; l < 2; l++) {
            As[kq[l] + 0][rw[l]] = aR[l].x;  As[kq[l] + 1][rw[l]] = aR[l].y;
            As[kq[l] + 2][rw[l]] = aR[l].z;  As[kq[l] + 3][rw[l]] = aR[l].w;
            Bs[kq[l] + 0][rw[l]] = bR[l].x;  Bs[kq[l] + 1][rw[l]] = bR[l].y;
            Bs[kq[l] + 2][rw[l]] = bR[l].z;  Bs[kq[l] + 3][rw[l]] = bR[l].w;
        }
        __syncthreads();
        if (kt + 1 < KT) {
            int ko = (kt + 1) * 16;
#pragma unroll
            for (int l = 0; l < 2; l++) {
                aR[l] = *(const float4*)(aP[l] + ko + kq[l]);
                bR[l] = *(const float4*)(bP[l] + ko + kq[l]);
            }
        }
#pragma unroll
        for (int k = 0; k < 16; k++) {
            float4 a0 = *(const float4*)&As[k][ty * 8];
            float4 a1 = *(const float4*)&As[k][ty * 8 + 4];
            ulonglong2 b01 = *(const ulonglong2*)&Bs[k][tx * 8];
            ulonglong2 b23 = *(const ulonglong2*)&Bs[k][tx * 8 + 4];
            unsigned long long bp[4] = {b01.x, b01.y, b23.x, b23.y};
            float am[8] = {a0.x, a0.y, a0.z, a0.w, a1.x, a1.y, a1.z, a1.w};
#pragma unroll
            for (int mi = 0; mi < 8; mi++) {
                unsigned long long ad = dup2(am[mi]);
#pragma unroll
                for (int np = 0; np < 4; np++)
                    acc[mi][np] = ffma2(ad, bp[np], acc[mi][np]);
            }
        }
        __syncthreads();
    }

    float* cbase = (MODE == 0) ? g_Xenc : g_Xdec;
#pragma unroll
    for (int mi = 0; mi < 8; mi++) {
        int rg = m0 + ty * 8 + mi;
        float* cptr = cbase + (size_t)rg * FOURH;
#pragma unroll
        for (int np = 0; np < 4; np++) {
            int n = n0 + tx * 8 + np * 2;
            float2 v = unpk(acc[mi][np]);
            float2 o; o.x = v.x + bias[n]; o.y = v.y + bias[n + 1];
            *(float2*)(cptr + n) = o;
        }
    }
}

// =====================================================================
// Persistent cluster LSTM, REGISTER-RESIDENT weights.
// 16 clusters x 8 CTAs x 256 threads. Cluster c: batches {2c,2c+1}.
// CTA rank r: gate rows for units [32r,32r+32) (128 rows).
// Thread (r = tid&127, kh = tid>>7) holds W[grow][kh*128 .. +128) as
// 64 packed f32x2 REGISTERS. Per-step dot reads ONLY h from SMEM via
// broadcast LDS.128 (h stored per-batch k-contiguous), zero movs:
//   acc_b += ffma2(wreg_i, h2_b_i)  -> horizontal add at end.
// k-halves merge + gate exchange through gbuf; owners (tid<64) keep c
// in regs, push new h to all 8 peers (mapa + st.shared::cluster),
// ONE barrier.cluster per step (double-buffered h).
// =====================================================================
__global__ __launch_bounds__(256) __cluster_dims__(CSIZE, 1, 1)
void lstm_kernel(const float* __restrict__ WhhE, const float* __restrict__ WhhD) {
    __shared__ __align__(16) float hSb[2][2][H_];    // [buf][batch][k]  4KB
    __shared__ __align__(16) float gbuf[128][2][2];  // [row][kh][batch] 2KB

    const int tid  = threadIdx.x;
    const uint32_t rank = ctarank();
    const int cid  = blockIdx.x >> 3;        // cluster id 0..15
    const int r    = tid & 127;              // gate row within CTA
    const int kh   = tid >> 7;               // k-half 0/1
    const int g    = r >> 5;                 // gate 0..3
    const int ul   = r & 31;                 // unit within CTA block
    const int grow = g * 256 + (int)rank * 32 + ul;   // global gate row
    const int b0   = cid * 2;                // global batch base

    const uint32_t hS_u32 = smem_u32(&hSb[0][0][0]);

    // zero both h buffers (own replica)
    ((float4*)&hSb[0][0][0])[tid] = make_float4(0.f, 0.f, 0.f, 0.f);
    cluster_sync();    // replicas zeroed cluster-wide before any DSMEM push

    float c = 0.f;     // cell state for owners (tid < 64)
    int stepIdx = 0;

    unsigned long long wreg[64];             // 128KB/CTA of Whh in registers

    for (int phase = 0; phase < 2; phase++) {
        // load this thread's weight slice into registers (amortized)
        {
            const float* wp = (phase ? WhhD : WhhE) + (size_t)grow * H_ + kh * 128;
#pragma unroll
            for (int i = 0; i < 64; i++)
                wreg[i] = *(const unsigned long long*)(wp + 2 * i);
        }

        const int nsteps = phase ? 63 : 64;
        const float* X = phase ? g_Xdec : g_Xenc;

        for (int s = 0; s < nsteps; s++) {
            const int p = stepIdx & 1;

            // x contributions (kh=0 threads; issued early, overlaps dot)
            float x0 = 0.f, x1 = 0.f;
            if (kh == 0) {
                size_t xr = (size_t)((s << 5) + b0) * FOURH + grow;
                x0 = X[xr];
                x1 = X[xr + FOURH];
            }

            // dot: only h comes from SMEM (pure broadcasts); weights in regs
            unsigned long long acc0 = 0ull, acc1 = 0ull;
            const ulonglong2* h0 = (const ulonglong2*)&hSb[p][0][kh * 128];
            const ulonglong2* h1 = (const ulonglong2*)&hSb[p][1][kh * 128];
#pragma unroll
            for (int i = 0; i < 32; i++) {
                ulonglong2 ha = h0[i];       // k-pairs 4i..4i+3, batch b0
                ulonglong2 hb = h1[i];       // same k, batch b0+1
                acc0 = ffma2(wreg[2 * i],     ha.x, acc0);
                acc0 = ffma2(wreg[2 * i + 1], ha.y, acc0);
                acc1 = ffma2(wreg[2 * i],     hb.x, acc1);
                acc1 = ffma2(wreg[2 * i + 1], hb.y, acc1);
            }
            float2 v0 = unpk(acc0), v1 = unpk(acc1);
            float pb0 = v0.x + v0.y + x0;    // partial preact, batch b0
            float pb1 = v1.x + v1.y + x1;    // partial preact, batch b0+1
            *(float2*)&gbuf[r][kh][0] = make_float2(pb0, pb1);
            __syncthreads();

            if (tid < 64) {                  // owner of (unit ul, batch bb)
                int uu = tid & 31;
                int bb = tid >> 5;           // 0 or 1
                float ig = gbuf[0 * 32 + uu][0][bb] + gbuf[0 * 32 + uu][1][bb];
                float fg = gbuf[1 * 32 + uu][0][bb] + gbuf[1 * 32 + uu][1][bb];
                float gg = gbuf[2 * 32 + uu][0][bb] + gbuf[2 * 32 + uu][1][bb];
                float og = gbuf[3 * 32 + uu][0][bb] + gbuf[3 * 32 + uu][1][bb];
                float si = 1.f / (1.f + __expf(-ig));
                float sf = 1.f / (1.f + __expf(-fg));
                float so = 1.f / (1.f + __expf(-og));
                c = sf * c + si * tanhf(gg);
                float hv = so * tanhf(c);

                // push to all 8 cluster CTAs' hSb[p^1][bb][ug]
                int ug = (int)rank * 32 + uu;
                uint32_t off = hS_u32 +
                    (uint32_t)(((p ^ 1) * 2 + bb) * H_ + ug) * 4u;
#pragma unroll
                for (int rr = 0; rr < CSIZE; rr++)
                    st_cluster_f32(off, (uint32_t)rr, hv);

                if (phase) g_hsT[ug][(s << 5) + b0 + bb] = hv;
            }

            // one cluster barrier per step (double buffering makes it safe)
            cluster_sync();
            stepIdx++;
        }
    }
}

// =====================================================================
// FC GEMM: g_hsT^T[2048,256] @ fc_W[32000,256]^T + fc_b -> scatter
// BM=128, BN=256, BK=16, 256 threads, 16x8 per-thread tile, f32x2.
// A from transposed g_hsT: coalesced LDG.128 + aligned STS.128
// (As stride 132 floats = 528B, 16B-aligned). B: 8B LDS (stride 258).
// =====================================================================
__global__ __launch_bounds__(256)
void fc_kernel(const float* __restrict__ Bmat, const float* __restrict__ bias,
               float* __restrict__ out) {
    __shared__ __align__(16) float As[16][132];
    __shared__ __align__(16) float Bs[16][258];

    const int tid = threadIdx.x;
    const int tx = tid & 31;        // N: cols tx*4..+3 and 128+tx*4..+3
    const int ty = tid >> 5;        // M: rows ty*16..+15
    const int n0 = blockIdx.x * 256;
    const int m0 = blockIdx.y * 128;

    // A loaders: 2 slots/thread from g_hsT[k][m] (row-contiguous in m)
    const float* aP[2]; int ak[2], aj[2];
#pragma unroll
    for (int l = 0; l < 2; l++) {
        int id = tid + l * 256;
        ak[l] = id >> 5;                  // k row 0..15
        aj[l] = id & 31;                  // m-chunk 0..31
        aP[l] = &g_hsT[ak[l]][m0 + aj[l] * 4];
    }
    // B loaders: 4 slots/thread
    const float* bP[4]; int bkq[4], brw[4];
#pragma unroll
    for (int l = 0; l < 4; l++) {
        int id = tid + l * 256;
        brw[l] = id >> 2;                 // 0..255
        bkq[l] = (id & 3) * 4;
        bP[l]  = Bmat + (size_t)(n0 + brw[l]) * H_ + bkq[l];
    }

    unsigned long long acc[16][4];
#pragma unroll
    for (int i = 0; i < 16; i++)
#pragma unroll
        for (int j = 0; j < 4; j++) acc[i][j] = 0ull;

    float4 aR[2], bR[4];
#pragma unroll
    for (int l = 0; l < 2; l++) aR[l] = *(const float4*)(aP[l]);
#pragma unroll
    for (int l = 0; l < 4; l++) bR[l] = *(const float4*)(bP[l]);

    const int KT = H_ / 16;   // 16 k-tiles
    for (int kt = 0; kt < KT; kt++) {
#pragma unroll
        for (int l = 0; l < 2; l++)
            *(float4*)&As[ak[l]][aj[l] * 4] = aR[l];     // aligned STS.128
#pragma unroll
        for (int l = 0; l < 4; l++) {
            Bs[bkq[l] + 0][brw[l]] = bR[l].x;  Bs[bkq[l] + 1][brw[l]] = bR[l].y;
            Bs[bkq[l] + 2][brw[l]] = bR[l].z;  Bs[bkq[l] + 3][brw[l]] = bR[l].w;
        }
        __syncthreads();
        if (kt + 1 < KT) {
#pragma unroll
            for (int l = 0; l < 2; l++)
                aR[l] = *(const float4*)(aP[l] + (size_t)(kt + 1) * 16 * MPAD);
            int ko = (kt + 1) * 16;
#pragma unroll
            for (int l = 0; l < 4; l++) bR[l] = *(const float4*)(bP[l] + ko);
        }
#pragma unroll
        for (int k = 0; k < 16; k++) {
            // B fragment: 8 cols as 4 packed pairs — 8B loads (8B-aligned all k)
            unsigned long long bp[4];
            bp[0] = *(const unsigned long long*)&Bs[k][tx * 4];
            bp[1] = *(const unsigned long long*)&Bs[k][tx * 4 + 2];
            bp[2] = *(const unsigned long long*)&Bs[k][128 + tx * 4];
            bp[3] = *(const unsigned long long*)&Bs[k][128 + tx * 4 + 2];
            // A fragment: 16 rows via 4 broadcast LDS.128 (16B-aligned)
            float4 a0 = *(const float4*)&As[k][ty * 16 + 0];
            float4 a1 = *(const float4*)&As[k][ty * 16 + 4];
            float4 a2 = *(const float4*)&As[k][ty * 16 + 8];
            float4 a3 = *(const float4*)&As[k][ty * 16 + 12];
            float am[16] = {a0.x, a0.y, a0.z, a0.w, a1.x, a1.y, a1.z, a1.w,
                            a2.x, a2.y, a2.z, a2.w, a3.x, a3.y, a3.z, a3.w};
#pragma unroll
            for (int mi = 0; mi < 16; mi++) {
                unsigned long long ad = dup2(am[mi]);
#pragma unroll
                for (int np = 0; np < 4; np++)
                    acc[mi][np] = ffma2(ad, bp[np], acc[mi][np]);
            }
        }
        __syncthreads();
    }

    // epilogue: bias + scatter out[b][t+1][v], skip pad rows (t=63)
    float4 bias0 = *(const float4*)(bias + n0 + tx * 4);
    float4 bias1 = *(const float4*)(bias + n0 + 128 + tx * 4);
#pragma unroll
    for (int mi = 0; mi < 16; mi++) {
        int rg = m0 + ty * 16 + mi;
        if (rg >= 2016) continue;
        int bb = rg & 31, t = rg >> 5;
        float* cptr = out + (size_t)bb * ((size_t)T_ * V_) + (size_t)(t + 1) * V_;
        float2 v0 = unpk(acc[mi][0]), v1 = unpk(acc[mi][1]);
        float2 v2 = unpk(acc[mi][2]), v3 = unpk(acc[mi][3]);
        float4 o0 = make_float4(v0.x + bias0.x, v0.y + bias0.y,
                                v1.x + bias0.z, v1.y + bias0.w);
        float4 o1 = make_float4(v2.x + bias1.x, v2.y + bias1.y,
                                v3.x + bias1.z, v3.y + bias1.w);
        *(float4*)(cptr + n0 + tx * 4)       = o0;
        *(float4*)(cptr + n0 + 128 + tx * 4) = o1;
    }
}

// =====================================================================
extern "C" void kernel_launch(void* const* d_in, const int* in_sizes, int n_in,
                              void* d_out, int out_size) {
    const int*   src  = (const int*)d_in[0];
    const int*   trg  = (const int*)d_in[1];
    const float* eemb = (const float*)d_in[2];
    const float* eWih = (const float*)d_in[3];
    const float* eWhh = (const float*)d_in[4];
    const float* eb   = (const float*)d_in[5];
    const float* demb = (const float*)d_in[6];
    const float* dWih = (const float*)d_in[7];
    const float* dWhh = (const float*)d_in[8];
    const float* db   = (const float*)d_in[9];
    const float* fcW  = (const float*)d_in[10];
    const float* fcb  = (const float*)d_in[11];
    float* out = (float*)d_out;

    init_kernel<<<256, 256>>>(out);
    xih_kernel<0><<<dim3(8, 16), 256>>>(eemb, src, eWih, eb);
    xih_kernel<1><<<dim3(8, 16), 256>>>(demb, trg, dWih, db);
    lstm_kernel<<<LSTM_CTAS, 256>>>(eWhh, dWhh);
    fc_kernel<<<dim3(125, 16), 256>>>(fcW, fcb, out);
}

// round 14
// speedup vs baseline: 1.7514x; 1.1251x over previous
#include <cuda_runtime.h>
#include <cstdint>

// Problem dims
#define B_ 32
#define S_ 64
#define T_ 64
#define E_ 128
#define H_ 256
#define V_ 32000
#define FOURH 1024
#define MPAD 2048   // padded row count for GEMM tiles (2016 real decoder rows)

// LSTM cluster config: 16 clusters x 8 CTAs; cluster owns 2 batches,
// CTA rank owns 32 hidden units (128 gate rows). Whh slice lives in
// REGISTERS: 256 threads x 64 f32x2 regs = 128KB per CTA.
#define CSIZE 8
#define LSTM_CTAS 128
// per-step bytes received per CTA: 8 CTAs x 64 owners x 4B
#define STEP_TX_BYTES 2048u

// -------- device scratch (allocation-free: __device__ globals) --------
__device__ __align__(16) float g_Xenc[MPAD * FOURH];   // enc_b + src_emb @ enc_Wih^T, rows r = s*32+b
__device__ __align__(16) float g_Xdec[MPAD * FOURH];   // dec_b + trg_emb @ dec_Wih^T, rows r = t*32+b
__device__ __align__(16) float g_hsT[H_][MPAD];        // decoder hidden TRANSPOSED: [u][t*32+b] (pad m>=2016 zeroed)

// -------- packed f32x2 helpers (sm_103a FFMA2 = full fp32 rate) --------
static __device__ __forceinline__ unsigned long long ffma2(unsigned long long a,
                                                           unsigned long long b,
                                                           unsigned long long c) {
    unsigned long long d;
    asm("fma.rn.f32x2 %0, %1, %2, %3;" : "=l"(d) : "l"(a), "l"(b), "l"(c));
    return d;
}
static __device__ __forceinline__ unsigned long long dup2(float a) {
    unsigned long long r;
    asm("mov.b64 %0, {%1, %1};" : "=l"(r) : "f"(a));
    return r;
}
static __device__ __forceinline__ float2 unpk(unsigned long long v) {
    float lo, hi;
    asm("mov.b64 {%0, %1}, %2;" : "=f"(lo), "=f"(hi) : "l"(v));
    return make_float2(lo, hi);
}

// -------- fast activations (MUFU-only; rel-err << 1e-3 budget) --------
static __device__ __forceinline__ float fsigmoid(float x) {
    return __fdividef(1.f, 1.f + __expf(-x));
}
static __device__ __forceinline__ float ftanh(float x) {
    return 1.f - __fdividef(2.f, __expf(2.f * x) + 1.f);
}

// -------- cluster / mbarrier helpers --------
static __device__ __forceinline__ uint32_t ctarank() {
    uint32_t r; asm("mov.u32 %0, %%cluster_ctarank;" : "=r"(r)); return r;
}
static __device__ __forceinline__ uint32_t smem_u32(const void* p) {
    uint32_t a;
    asm("{ .reg .u64 t; cvta.to.shared.u64 t, %1; cvt.u32.u64 %0, t; }"
        : "=r"(a) : "l"(p));
    return a;
}
static __device__ __forceinline__ void cluster_sync() {
    asm volatile("barrier.cluster.arrive.aligned;" ::: "memory");
    asm volatile("barrier.cluster.wait.aligned;" ::: "memory");
}
static __device__ __forceinline__ void mbar_init(uint32_t mbar, uint32_t cnt) {
    asm volatile("mbarrier.init.shared.b64 [%0], %1;" :: "r"(mbar), "r"(cnt) : "memory");
}
static __device__ __forceinline__ void mbar_expect_tx(uint32_t mbar, uint32_t bytes) {
    asm volatile("mbarrier.arrive.expect_tx.shared.b64 _, [%0], %1;"
                 :: "r"(mbar), "r"(bytes) : "memory");
}
static __device__ __forceinline__ void mbar_wait_parity(uint32_t mbar, uint32_t parity) {
    uint32_t done;
    asm volatile(
        "{\n\t.reg .pred p;\n\t"
        "mbarrier.try_wait.parity.acquire.cta.shared::cta.b64 p, [%1], %2;\n\t"
        "selp.b32 %0, 1, 0, p;\n\t}"
        : "=r"(done) : "r"(mbar), "r"(parity) : "memory");
    if (!done) {
        asm volatile(
            "{\n\t.reg .pred P1;\n\t"
            "WAIT_LOOP_%=:\n\t"
            "mbarrier.try_wait.parity.acquire.cta.shared::cta.b64 P1, [%0], %1, 0x989680;\n\t"
            "@P1 bra.uni WAIT_DONE_%=;\n\t"
            "bra.uni WAIT_LOOP_%=;\n\t"
            "WAIT_DONE_%=:\n\t}"
            :: "r"(mbar), "r"(parity) : "memory");
    }
}
// remote store with mbarrier transaction completion (async proxy)
static __device__ __forceinline__ void st_async_f32(uint32_t data_l, uint32_t mbar_l,
                                                    uint32_t rank, float v) {
    uint32_t rd, rm;
    asm volatile("mapa.shared::cluster.u32 %0, %1, %2;" : "=r"(rd) : "r"(data_l), "r"(rank));
    asm volatile("mapa.shared::cluster.u32 %0, %1, %2;" : "=r"(rm) : "r"(mbar_l), "r"(rank));
    asm volatile("st.async.shared::cluster.mbarrier::complete_tx::bytes.b32 [%0], %1, [%2];"
                 :: "r"(rd), "r"(__float_as_uint(v)), "r"(rm) : "memory");
}

// =====================================================================
// init: zero g_hsT pad rows, zero out[:, 0, :]
// =====================================================================
__global__ void init_kernel(float* __restrict__ out) {
    int gt = blockIdx.x * blockDim.x + threadIdx.x;
    if (gt < H_ * 32) {                          // g_hsT[u][2016..2047] = 0
        int u = gt >> 5, m = 2016 + (gt & 31);
        g_hsT[u][m] = 0.f;
    }
    const int total = B_ * (V_ / 4);
    for (int i = gt; i < total; i += gridDim.x * blockDim.x) {
        int b  = i / (V_ / 4);
        int v4 = i - b * (V_ / 4);
        ((float4*)(out + (size_t)b * T_ * V_))[v4] = make_float4(0.f, 0.f, 0.f, 0.f);
    }
}

// =====================================================================
// Xih precompute GEMM  C[2048,1024] = gathered_emb @ Wih^T (+bias)
//   MODE 0: idx=src -> g_Xenc;  MODE 1: idx=trg (t clamped) -> g_Xdec
// BM=BN=128, BK=16, 256 threads, 8x8/thread, f32x2. Stride 132 (16B ok).
// =====================================================================
template <int MODE>
__global__ __launch_bounds__(256)
void xih_kernel(const float* __restrict__ Amat, const int* __restrict__ idx,
                const float* __restrict__ Bmat, const float* __restrict__ bias) {
    const int KD = 128;
    __shared__ __align__(16) float As[16][132];
    __shared__ __align__(16) float Bs[16][132];

    const int tid = threadIdx.x;
    const int tx = tid & 15;
    const int ty = tid >> 4;
    const int n0 = blockIdx.x * 128;
    const int m0 = blockIdx.y * 128;

    const float* aP[2];
    const float* bP[2];
    int kq[2], rw[2];
#pragma unroll
    for (int l = 0; l < 2; l++) {
        int id = tid + l * 256;
        int r  = id >> 2;
        kq[l]  = (id & 3) * 4;
        rw[l]  = r;
        int rg = m0 + r;
        int tt = rg >> 5, bb = rg & 31;
        if (MODE == 1 && tt > 62) tt = 62;   // pad rows: garbage ok, never read
        aP[l] = Amat + (size_t)idx[bb * 64 + tt] * KD;
        bP[l] = Bmat + (size_t)(n0 + r) * KD;
    }

    unsigned long long acc[8][4];
#pragma unroll
    for (int i = 0; i < 8; i++)
#pragma unroll
        for (int j = 0; j < 4; j++) acc[i][j] = 0ull;

    float4 aR[2], bR[2];
#pragma unroll
    for (int l = 0; l < 2; l++) {
        aR[l] = *(const float4*)(aP[l] + kq[l]);
        bR[l] = *(const float4*)(bP[l] + kq[l]);
    }

    const int KT = KD / 16;
    for (int kt = 0; kt < KT; kt++) {
#pragma unroll
        for (int l = 0; l < 2; l++) {
            As[kq[l] + 0][rw[l]] = aR[l].x;  As[kq[l] + 1][rw[l]] = aR[l].y;
            As[kq[l] + 2][rw[l]] = aR[l].z;  As[kq[l] + 3][rw[l]] = aR[l].w;
            Bs[kq[l] + 0][rw[l]] = bR[l].x;  Bs[kq[l] + 1][rw[l]] = bR[l].y;
            Bs[kq[l] + 2][rw[l]] = bR[l].z;  Bs[kq[l] + 3][rw[l]] = bR[l].w;
        }
        __syncthreads();
        if (kt + 1 < KT) {
            int ko = (kt + 1) * 16;
#pragma unroll
            for (int l = 0; l < 2; l++) {
                aR[l] = *(const float4*)(aP[l] + ko + kq[l]);
                bR[l] = *(const float4*)(bP[l] + ko + kq[l]);
            }
        }
#pragma unroll
        for (int k = 0; k < 16; k++) {
            float4 a0 = *(const float4*)&As[k][ty * 8];
            float4 a1 = *(const float4*)&As[k][ty * 8 + 4];
            ulonglong2 b01 = *(const ulonglong2*)&Bs[k][tx * 8];
            ulonglong2 b23 = *(const ulonglong2*)&Bs[k][tx * 8 + 4];
            unsigned long long bp[4] = {b01.x, b01.y, b23.x, b23.y};
            float am[8] = {a0.x, a0.y, a0.z, a0.w, a1.x, a1.y, a1.z, a1.w};
#pragma unroll
            for (int mi = 0; mi < 8; mi++) {
                unsigned long long ad = dup2(am[mi]);
#pragma unroll
                for (int np = 0; np < 4; np++)
                    acc[mi][np] = ffma2(ad, bp[np], acc[mi][np]);
            }
        }
        __syncthreads();
    }

    float* cbase = (MODE == 0) ? g_Xenc : g_Xdec;
#pragma unroll
    for (int mi = 0; mi < 8; mi++) {
        int rg = m0 + ty * 8 + mi;
        float* cptr = cbase + (size_t)rg * FOURH;
#pragma unroll
        for (int np = 0; np < 4; np++) {
            int n = n0 + tx * 8 + np * 2;
            float2 v = unpk(acc[mi][np]);
            float2 o; o.x = v.x + bias[n]; o.y = v.y + bias[n + 1];
            *(float2*)(cptr + n) = o;
        }
    }
}

// =====================================================================
// Persistent cluster LSTM: register-resident weights + st.async flow
// control (NO per-step cluster barrier).
// 16 clusters x 8 CTAs x 256 threads. Cluster c: batches {2c,2c+1}.
// Thread (r=tid&127, kh=tid>>7) holds W[grow][kh*128..+128) as 64 f32x2
// regs. Dot reads only h (broadcast LDS.128). Owners (tid<64) push new
// h to all 8 peer replicas via st.async, each push counting 4 tx bytes
// on the receiver's per-buffer mbarrier; consumers try_wait locally for
// 2048 bytes. Sending h_s proves the sender finished reading the buffer
// step s+1 overwrites -> 2-deep buffering is safe with full-barriers
// only. gbuf reuse is ordered by the same wait.
// =====================================================================
__global__ __launch_bounds__(256) __cluster_dims__(CSIZE, 1, 1)
void lstm_kernel(const float* __restrict__ WhhE, const float* __restrict__ WhhD) {
    __shared__ __align__(16) float hSb[2][2][H_];       // [buf][batch][k]  4KB
    __shared__ __align__(16) float gbuf[128][2][2];     // [row][kh][batch] 2KB
    __shared__ __align__(8) unsigned long long mbar[2]; // per-buffer tx barrier

    const int tid  = threadIdx.x;
    const uint32_t rank = ctarank();
    const int cid  = blockIdx.x >> 3;        // cluster id 0..15
    const int r    = tid & 127;              // gate row within CTA
    const int kh   = tid >> 7;               // k-half 0/1
    const int g    = r >> 5;                 // gate 0..3
    const int ul   = r & 31;                 // unit within CTA block
    const int grow = g * 256 + (int)rank * 32 + ul;   // global gate row
    const int b0   = cid * 2;                // global batch base

    const uint32_t hS_u32 = smem_u32(&hSb[0][0][0]);
    const uint32_t mb_u32 = smem_u32(&mbar[0]);

    // zero both h replicas; init per-buffer mbarriers (count=1: the
    // expect_tx arrive is the only arrival; completion is tx-driven)
    ((float4*)&hSb[0][0][0])[tid] = make_float4(0.f, 0.f, 0.f, 0.f);
    if (tid == 0) { mbar_init(mb_u32, 1); mbar_init(mb_u32 + 8, 1); }
    cluster_sync();   // replicas zeroed + barriers visible cluster-wide

    float c = 0.f;                // cell state for owners (tid < 64)
    int ph[2] = {0, 0};           // per-buffer wait parity
    int stepIdx = 0;

    unsigned long long wreg[64];  // 128KB/CTA of Whh in registers

    for (int phase = 0; phase < 2; phase++) {
        {   // load this thread's weight slice (amortized over the phase)
            const float* wp = (phase ? WhhD : WhhE) + (size_t)grow * H_ + kh * 128;
#pragma unroll
            for (int i = 0; i < 64; i++)
                wreg[i] = *(const unsigned long long*)(wp + 2 * i);
        }

        const int nsteps = phase ? 63 : 64;
        const float* X = phase ? g_Xdec : g_Xenc;

        for (int s = 0; s < nsteps; s++) {
            const int p = stepIdx & 1;

            // post expectation for the buffer written this step (p^1)
            if (tid == 0) mbar_expect_tx(mb_u32 + 8u * (unsigned)(p ^ 1), STEP_TX_BYTES);

            // x contributions: independent of h -> issue before the wait
            float x0 = 0.f, x1 = 0.f;
            if (kh == 0) {
                size_t xr = (size_t)((s << 5) + b0) * FOURH + grow;
                x0 = X[xr];
                x1 = X[xr + FOURH];
            }

            // wait for buffer p to be full (skip bootstrap step 0)
            if (stepIdx > 0) {
                mbar_wait_parity(mb_u32 + 8u * (unsigned)p, (uint32_t)ph[p]);
                ph[p] ^= 1;
            }

            // dot: only h from SMEM (pure broadcasts); weights in regs
            unsigned long long acc0 = 0ull, acc1 = 0ull;
            const ulonglong2* h0 = (const ulonglong2*)&hSb[p][0][kh * 128];
            const ulonglong2* h1 = (const ulonglong2*)&hSb[p][1][kh * 128];
#pragma unroll
            for (int i = 0; i < 32; i++) {
                ulonglong2 ha = h0[i];       // k-pairs 4i..4i+3, batch b0
                ulonglong2 hb = h1[i];       // same k, batch b0+1
                acc0 = ffma2(wreg[2 * i],     ha.x, acc0);
                acc0 = ffma2(wreg[2 * i + 1], ha.y, acc0);
                acc1 = ffma2(wreg[2 * i],     hb.x, acc1);
                acc1 = ffma2(wreg[2 * i + 1], hb.y, acc1);
            }
            float2 v0 = unpk(acc0), v1 = unpk(acc1);
            *(float2*)&gbuf[r][kh][0] =
                make_float2(v0.x + v0.y + x0, v1.x + v1.y + x1);
            __syncthreads();

            if (tid < 64) {                  // owner of (unit ul, batch bb)
                int uu = tid & 31;
                int bb = tid >> 5;           // 0 or 1
                float ig = gbuf[0 * 32 + uu][0][bb] + gbuf[0 * 32 + uu][1][bb];
                float fg = gbuf[1 * 32 + uu][0][bb] + gbuf[1 * 32 + uu][1][bb];
                float gg = gbuf[2 * 32 + uu][0][bb] + gbuf[2 * 32 + uu][1][bb];
                float og = gbuf[3 * 32 + uu][0][bb] + gbuf[3 * 32 + uu][1][bb];
                c = fsigmoid(fg) * c + fsigmoid(ig) * ftanh(gg);
                float hv = fsigmoid(og) * ftanh(c);

                // push to all 8 cluster replicas, counting tx on each
                // receiver's mbar[p^1]
                int ug = (int)rank * 32 + uu;
                uint32_t doff = hS_u32 +
                    (uint32_t)(((p ^ 1) * 2 + bb) * H_ + ug) * 4u;
                uint32_t moff = mb_u32 + 8u * (unsigned)(p ^ 1);
#pragma unroll
                for (int rr = 0; rr < CSIZE; rr++)
                    st_async_f32(doff, moff, (uint32_t)rr, hv);

                if (phase) g_hsT[ug][(s << 5) + b0 + bb] = hv;
            }
            stepIdx++;
        }
    }

    // keep SMEM alive until every CTA's in-flight st.async has landed
    cluster_sync();
}

// =====================================================================
// FC GEMM: g_hsT^T[2048,256] @ fc_W[32000,256]^T + fc_b -> scatter
// BM=128, BN=256, BK=16, 256 threads, 16x8 per-thread tile, f32x2.
// A from transposed g_hsT: coalesced LDG.128 + aligned STS.128
// (As stride 132 floats = 528B, 16B-aligned). B: 8B LDS (stride 258).
// =====================================================================
__global__ __launch_bounds__(256)
void fc_kernel(const float* __restrict__ Bmat, const float* __restrict__ bias,
               float* __restrict__ out) {
    __shared__ __align__(16) float As[16][132];
    __shared__ __align__(16) float Bs[16][258];

    const int tid = threadIdx.x;
    const int tx = tid & 31;        // N: cols tx*4..+3 and 128+tx*4..+3
    const int ty = tid >> 5;        // M: rows ty*16..+15
    const int n0 = blockIdx.x * 256;
    const int m0 = blockIdx.y * 128;

    // A loaders: 2 slots/thread from g_hsT[k][m] (row-contiguous in m)
    const float* aP[2]; int ak[2], aj[2];
#pragma unroll
    for (int l = 0; l < 2; l++) {
        int id = tid + l * 256;
        ak[l] = id >> 5;                  // k row 0..15
        aj[l] = id & 31;                  // m-chunk 0..31
        aP[l] = &g_hsT[ak[l]][m0 + aj[l] * 4];
    }
    // B loaders: 4 slots/thread
    const float* bP[4]; int bkq[4], brw[4];
#pragma unroll
    for (int l = 0; l < 4; l++) {
        int id = tid + l * 256;
        brw[l] = id >> 2;                 // 0..255
        bkq[l] = (id & 3) * 4;
        bP[l]  = Bmat + (size_t)(n0 + brw[l]) * H_ + bkq[l];
    }

    unsigned long long acc[16][4];
#pragma unroll
    for (int i = 0; i < 16; i++)
#pragma unroll
        for (int j = 0; j < 4; j++) acc[i][j] = 0ull;

    float4 aR[2], bR[4];
#pragma unroll
    for (int l = 0; l < 2; l++) aR[l] = *(const float4*)(aP[l]);
#pragma unroll
    for (int l = 0; l < 4; l++) bR[l] = *(const float4*)(bP[l]);

    const int KT = H_ / 16;   // 16 k-tiles
    for (int kt = 0; kt < KT; kt++) {
#pragma unroll
        for (int l = 0; l < 2; l++)
            *(float4*)&As[ak[l]][aj[l] * 4] = aR[l];     // aligned STS.128
#pragma unroll
        for (int l = 0; l < 4; l++) {
            Bs[bkq[l] + 0][brw[l]] = bR[l].x;  Bs[bkq[l] + 1][brw[l]] = bR[l].y;
            Bs[bkq[l] + 2][brw[l]] = bR[l].z;  Bs[bkq[l] + 3][brw[l]] = bR[l].w;
        }
        __syncthreads();
        if (kt + 1 < KT) {
#pragma unroll
            for (int l = 0; l < 2; l++)
                aR[l] = *(const float4*)(aP[l] + (size_t)(kt + 1) * 16 * MPAD);
            int ko = (kt + 1) * 16;
#pragma unroll
            for (int l = 0; l < 4; l++) bR[l] = *(const float4*)(bP[l] + ko);
        }
#pragma unroll
        for (int k = 0; k < 16; k++) {
            // B fragment: 8 cols as 4 packed pairs — 8B loads (8B-aligned all k)
            unsigned long long bp[4];
            bp[0] = *(const unsigned long long*)&Bs[k][tx * 4];
            bp[1] = *(const unsigned long long*)&Bs[k][tx * 4 + 2];
            bp[2] = *(const unsigned long long*)&Bs[k][128 + tx * 4];
            bp[3] = *(const unsigned long long*)&Bs[k][128 + tx * 4 + 2];
            // A fragment: 16 rows via 4 broadcast LDS.128 (16B-aligned)
            float4 a0 = *(const float4*)&As[k][ty * 16 + 0];
            float4 a1 = *(const float4*)&As[k][ty * 16 + 4];
            float4 a2 = *(const float4*)&As[k][ty * 16 + 8];
            float4 a3 = *(const float4*)&As[k][ty * 16 + 12];
            float am[16] = {a0.x, a0.y, a0.z, a0.w, a1.x, a1.y, a1.z, a1.w,
                            a2.x, a2.y, a2.z, a2.w, a3.x, a3.y, a3.z, a3.w};
#pragma unroll
            for (int mi = 0; mi < 16; mi++) {
                unsigned long long ad = dup2(am[mi]);
#pragma unroll
                for (int np = 0; np < 4; np++)
                    acc[mi][np] = ffma2(ad, bp[np], acc[mi][np]);
            }
        }
        __syncthreads();
    }

    // epilogue: bias + scatter out[b][t+1][v], skip pad rows (t=63)
    float4 bias0 = *(const float4*)(bias + n0 + tx * 4);
    float4 bias1 = *(const float4*)(bias + n0 + 128 + tx * 4);
#pragma unroll
    for (int mi = 0; mi < 16; mi++) {
        int rg = m0 + ty * 16 + mi;
        if (rg >= 2016) continue;
        int bb = rg & 31, t = rg >> 5;
        float* cptr = out + (size_t)bb * ((size_t)T_ * V_) + (size_t)(t + 1) * V_;
        float2 v0 = unpk(acc[mi][0]), v1 = unpk(acc[mi][1]);
        float2 v2 = unpk(acc[mi][2]), v3 = unpk(acc[mi][3]);
        float4 o0 = make_float4(v0.x + bias0.x, v0.y + bias0.y,
                                v1.x + bias0.z, v1.y + bias0.w);
        float4 o1 = make_float4(v2.x + bias1.x, v2.y + bias1.y,
                                v3.x + bias1.z, v3.y + bias1.w);
        *(float4*)(cptr + n0 + tx * 4)       = o0;
        *(float4*)(cptr + n0 + 128 + tx * 4) = o1;
    }
}

// =====================================================================
extern "C" void kernel_launch(void* const* d_in, const int* in_sizes, int n_in,
                              void* d_out, int out_size) {
    const int*   src  = (const int*)d_in[0];
    const int*   trg  = (const int*)d_in[1];
    const float* eemb = (const float*)d_in[2];
    const float* eWih = (const float*)d_in[3];
    const float* eWhh = (const float*)d_in[4];
    const float* eb   = (const float*)d_in[5];
    const float* demb = (const float*)d_in[6];
    const float* dWih = (const float*)d_in[7];
    const float* dWhh = (const float*)d_in[8];
    const float* db   = (const float*)d_in[9];
    const float* fcW  = (const float*)d_in[10];
    const float* fcb  = (const float*)d_in[11];
    float* out = (float*)d_out;

    init_kernel<<<256, 256>>>(out);
    xih_kernel<0><<<dim3(8, 16), 256>>>(eemb, src, eWih, eb);
    xih_kernel<1><<<dim3(8, 16), 256>>>(demb, trg, dWih, db);
    lstm_kernel<<<LSTM_CTAS, 256>>>(eWhh, dWhh);
    fc_kernel<<<dim3(125, 16), 256>>>(fcW, fcb, out);
}